// round 13
// baseline (speedup 1.0000x reference)
#include <cuda_runtime.h>
#include <cstdint>

// Problem constants
#define B_   2
#define QL_  512
#define KL_  8192
#define D_   1024
#define H_   8
#define HD_  128

// Scratch (device globals — no allocations allowed)
__device__ float g_Q[B_ * QL_ * D_];
__device__ float g_K[B_ * KL_ * D_];
__device__ float g_V[B_ * KL_ * D_];
__device__ float g_O[B_ * QL_ * D_];

// fp32 -> tf32 round-to-nearest (unbiased)
__device__ __forceinline__ uint32_t tf32r(float x) {
    uint32_t u;
    asm("cvt.rna.tf32.f32 %0, %1;" : "=r"(u) : "f"(x));
    return u;
}
__device__ __forceinline__ float tf32rf(float x) {
    return __uint_as_float(tf32r(x));
}
__device__ __forceinline__ uint32_t tf32ru(uint32_t x) {
    return tf32r(__uint_as_float(x));
}
__device__ __forceinline__ uint32_t smem_u32(const void* p) {
    uint32_t a;
    asm("{ .reg .u64 t; cvta.to.shared.u64 t, %1; cvt.u32.u64 %0, t; }"
        : "=r"(a) : "l"(p));
    return a;
}

// m16n8k8 tf32 MMA
__device__ __forceinline__ void mma_tf32(float* c, const uint32_t* a,
                                         const uint32_t* b) {
    asm volatile(
        "mma.sync.aligned.m16n8k8.row.col.f32.tf32.tf32.f32 "
        "{%0,%1,%2,%3}, {%4,%5,%6,%7}, {%8,%9}, {%0,%1,%2,%3};"
        : "+f"(c[0]), "+f"(c[1]), "+f"(c[2]), "+f"(c[3])
        : "r"(a[0]), "r"(a[1]), "r"(a[2]), "r"(a[3]), "r"(b[0]), "r"(b[1]));
}

#define CPA16(dst, src) \
    asm volatile("cp.async.cg.shared.global [%0], [%1], 16;" \
                 :: "r"(dst), "l"(src) : "memory")
#define CPA_COMMIT() asm volatile("cp.async.commit_group;" ::: "memory")
#define CPA_WAIT(n)  asm volatile("cp.async.wait_group %0;" :: "n"(n) : "memory")

// ===========================================================================
// tf32 mma.sync GEMM v3: 3-stage cp.async pipeline on RAW fp32 inputs;
// tf32 rounding applied at fragment load (rna, idempotent — numerically
// identical to the prepass it replaces). 2 CTAs/SM.
// C[M,N] = rna(A[M,K]) @ rna(W[N,K])^T + bias; round_store=1 -> tf32 out.
// ===========================================================================
#define KC    32
#define APAD  36
#define STW   (128 * APAD)
#define GEMM_SMEM (6 * STW * 4)

__global__ __launch_bounds__(256, 2) void gemm_tf32(
    const float* __restrict__ A, const float* __restrict__ W,
    const float* __restrict__ bias, float* __restrict__ C,
    int M, int N, int K, int round_store)
{
    extern __shared__ __align__(16) uint32_t sg[];
    const uint32_t sb = smem_u32(sg);
    const uint32_t B_OFF = 3 * STW * 4;
    const uint32_t ST_B  = STW * 4;

    const int t = threadIdx.x, wid = t >> 5, lane = t & 31;
    const int g = lane >> 2, t4 = lane & 3;
    const int m0 = blockIdx.y * 128, n0 = blockIdx.x * 128;
    const int mw = (wid >> 2) * 64;
    const int nw = (wid & 3) * 32;

    float acc[4][4][4];
#pragma unroll
    for (int mt = 0; mt < 4; mt++)
#pragma unroll
        for (int nt = 0; nt < 4; nt++)
#pragma unroll
            for (int q = 0; q < 4; q++) acc[mt][nt][q] = 0.f;

    const int r  = t >> 3;
    const int c4 = (t & 7) * 4;
    size_t   gA[4], gB[4];
    uint32_t so4[4];
#pragma unroll
    for (int i = 0; i < 4; i++) {
        int ri = r + i * 32;
        gA[i]  = (size_t)(m0 + ri) * K + c4;
        gB[i]  = (size_t)(n0 + ri) * K + c4;
        so4[i] = (uint32_t)(ri * APAD + c4) * 4;
    }

    const int NC = K / KC;

#pragma unroll
    for (int s = 0; s < 2; s++) {
#pragma unroll
        for (int i = 0; i < 4; i++) {
            CPA16(sb + s * ST_B + so4[i],         A + gA[i] + s * KC);
            CPA16(sb + B_OFF + s * ST_B + so4[i], W + gB[i] + s * KC);
        }
        CPA_COMMIT();
    }

    for (int c = 0; c < NC; c++) {
        if (c + 1 < NC) { CPA_WAIT(1); } else { CPA_WAIT(0); }
        __syncthreads();

        if (c + 2 < NC) {
            const int st = (c + 2) % 3;
            const size_t k2 = (size_t)(c + 2) * KC;
#pragma unroll
            for (int i = 0; i < 4; i++) {
                CPA16(sb + st * ST_B + so4[i],         A + gA[i] + k2);
                CPA16(sb + B_OFF + st * ST_B + so4[i], W + gB[i] + k2);
            }
            CPA_COMMIT();
        }

        const uint32_t* Ab = sg + (c % 3) * STW;
        const uint32_t* Bb = sg + 3 * STW + (c % 3) * STW;
#pragma unroll
        for (int ks = 0; ks < 4; ks++) {
            const int kb = ks * 8;
            uint32_t af[4][4], bf[4][2];
#pragma unroll
            for (int mt = 0; mt < 4; mt++) {
                const uint32_t* p = Ab + (mw + mt * 16 + g) * APAD + kb + t4;
                af[mt][0] = tf32ru(p[0]);
                af[mt][1] = tf32ru(p[8 * APAD]);
                af[mt][2] = tf32ru(p[4]);
                af[mt][3] = tf32ru(p[8 * APAD + 4]);
            }
#pragma unroll
            for (int nt = 0; nt < 4; nt++) {
                const uint32_t* p = Bb + (nw + nt * 8 + g) * APAD + kb + t4;
                bf[nt][0] = tf32ru(p[0]);
                bf[nt][1] = tf32ru(p[4]);
            }
#pragma unroll
            for (int mt = 0; mt < 4; mt++)
#pragma unroll
                for (int nt = 0; nt < 4; nt++)
                    mma_tf32(acc[mt][nt], af[mt], bf[nt]);
        }
    }

#pragma unroll
    for (int mt = 0; mt < 4; mt++) {
#pragma unroll
        for (int nt = 0; nt < 4; nt++) {
            const int row = m0 + mw + mt * 16 + g;
            const int col = n0 + nw + nt * 8 + 2 * t4;
            float2 bb = *(const float2*)(bias + col);
            float o0 = acc[mt][nt][0] + bb.x, o1 = acc[mt][nt][1] + bb.y;
            float o2 = acc[mt][nt][2] + bb.x, o3 = acc[mt][nt][3] + bb.y;
            if (round_store) {
                o0 = tf32rf(o0); o1 = tf32rf(o1);
                o2 = tf32rf(o2); o3 = tf32rf(o3);
            }
            *(float2*)(C + (size_t)row * N + col) = make_float2(o0, o1);
            *(float2*)(C + (size_t)(row + 8) * N + col) = make_float2(o2, o3);
        }
    }
}

// ===========================================================================
// Flash attention v4: Q fragments in registers + ONE barrier per tile.
// Loop order: WAIT(0) -> syncthreads -> issue prefetch(c+1) -> compute.
// The barrier that publishes tile c's data also proves all warps finished
// reading buffer (c+1)&1 (read during iter c-1), so the trailing barrier is
// dead. Prefetch still overlaps the whole tile's compute.
// 256 threads, 8 warps = 4 q-groups x 2 kv-strips; KT=64 double-buffered.
// ===========================================================================
#define QT   64
#define KT   64
#define QP   132
#define KP   132
#define VP   132
#define KBUF (KT * KP)
#define VBUF (KT * VP)
#define FL_WORDS (QT * QP + 2 * KBUF + 2 * VBUF)  // 42240
#define FL_SMEM  (FL_WORDS * 4)                   // 168960

__global__ __launch_bounds__(256, 1) void flash_mma(
    const int* __restrict__ mask, float* __restrict__ O)
{
    extern __shared__ __align__(16) uint32_t sf[];
    uint32_t* Qs = sf;
    uint32_t* Ks = sf + QT * QP;
    uint32_t* Vs = sf + QT * QP + 2 * KBUF;
    const uint32_t sb   = smem_u32(sf);
    const uint32_t ks_b = sb + QT * QP * 4;
    const uint32_t vs_b = sb + (QT * QP + 2 * KBUF) * 4;

    const int b  = blockIdx.x >> 3, h = blockIdx.x & 7;
    const int q0 = blockIdx.y * QT;
    const int t = threadIdx.x, wid = t >> 5, lane = t & 31;
    const int g = lane >> 2, t4 = lane & 3;
    const int qw = wid >> 1;
    const int kw = wid & 1;
    const int qrow = qw * 16 + g;

    // Load Q tile to SMEM
    {
        const size_t qbase = (size_t)(b * QL_ + q0) * D_ + h * HD_;
#pragma unroll
        for (int i = 0; i < 8; i++) {
            int v = t + i * 256, r = v >> 5, d4 = (v & 31) << 2;
            *(uint4*)(Qs + r * QP + d4) =
                *(const uint4*)(g_Q + qbase + (size_t)r * D_ + d4);
        }
    }
    __syncthreads();

    // Q fragments -> registers, once (loop-invariant)
    uint32_t qf[16][4];
#pragma unroll
    for (int ks = 0; ks < 16; ks++) {
        const uint32_t* qp = Qs + qrow * QP + ks * 8 + t4;
        qf[ks][0] = qp[0];
        qf[ks][1] = qp[8 * QP];
        qf[ks][2] = qp[4];
        qf[ks][3] = qp[8 * QP + 4];
    }

    const int lr  = t >> 5;
    const int ld4 = (t & 31) << 2;
    const size_t kvbase = (size_t)(b * KL_) * D_ + h * HD_;

    float acc[16][4];
#pragma unroll
    for (int dt = 0; dt < 16; dt++)
#pragma unroll
        for (int q = 0; q < 4; q++) acc[dt][q] = 0.f;
    float mrow[2] = {-1e30f, -1e30f}, lrow[2] = {0.f, 0.f};

    const float scale = 0.08838834764831845f;
    const int* mp0 = mask + (size_t)(b * QL_ + q0 + qrow) * KL_;
    const int* mp1 = mp0 + 8 * KL_;

    // prologue: tile 0 -> buf 0
#pragma unroll
    for (int i = 0; i < 8; i++) {
        int r = lr + i * 8;
        CPA16(ks_b + (r * KP + ld4) * 4, g_K + kvbase + (size_t)r * D_ + ld4);
    }
#pragma unroll
    for (int i = 0; i < 8; i++) {
        int r = lr + i * 8;
        CPA16(vs_b + (r * VP + ld4) * 4, g_V + kvbase + (size_t)r * D_ + ld4);
    }
    CPA_COMMIT();

    const int NT = KL_ / KT;   // 128
    for (int c = 0; c < NT; c++) {
        CPA_WAIT(0);
        __syncthreads();   // tile c visible; all warps done reading buf (c+1)&1

        if (c + 1 < NT) {
            const int buf = (c + 1) & 1;
            const size_t rb = kvbase + (size_t)(c + 1) * KT * D_;
#pragma unroll
            for (int i = 0; i < 8; i++) {
                int r = lr + i * 8;
                CPA16(ks_b + (buf * KBUF + r * KP + ld4) * 4,
                      g_K + rb + (size_t)r * D_ + ld4);
            }
#pragma unroll
            for (int i = 0; i < 8; i++) {
                int r = lr + i * 8;
                CPA16(vs_b + (buf * VBUF + r * VP + ld4) * 4,
                      g_V + rb + (size_t)r * D_ + ld4);
            }
            CPA_COMMIT();
        }

        const uint32_t* Kb = Ks + (c & 1) * KBUF;
        const uint32_t* Vb = Vs + (c & 1) * VBUF;
        const int kvt = c * KT + kw * 32;

        int2 mk0[4], mk1[4];
#pragma unroll
        for (int nt = 0; nt < 4; nt++) {
            const int col = kvt + nt * 8 + 2 * t4;
            mk0[nt] = *(const int2*)(mp0 + col);
            mk1[nt] = *(const int2*)(mp1 + col);
        }

        // S = Q . K^T (Q from registers)
        float s[4][4];
#pragma unroll
        for (int nt = 0; nt < 4; nt++)
#pragma unroll
            for (int q = 0; q < 4; q++) s[nt][q] = 0.f;
#pragma unroll
        for (int ks = 0; ks < 16; ks++) {
            const int kb = ks * 8;
#pragma unroll
            for (int nt = 0; nt < 4; nt++) {
                const uint32_t* kp = Kb + (kw * 32 + nt * 8 + g) * KP + kb + t4;
                uint32_t bf[2] = { kp[0], kp[4] };
                mma_tf32(s[nt], qf[ks], bf);
            }
        }

        // mask + online softmax
        float mx0 = -1e30f, mx1 = -1e30f;
        float sv[4][4];
#pragma unroll
        for (int nt = 0; nt < 4; nt++) {
            sv[nt][0] = mk0[nt].x ? s[nt][0] * scale : -1e30f;
            sv[nt][1] = mk0[nt].y ? s[nt][1] * scale : -1e30f;
            sv[nt][2] = mk1[nt].x ? s[nt][2] * scale : -1e30f;
            sv[nt][3] = mk1[nt].y ? s[nt][3] * scale : -1e30f;
            mx0 = fmaxf(mx0, fmaxf(sv[nt][0], sv[nt][1]));
            mx1 = fmaxf(mx1, fmaxf(sv[nt][2], sv[nt][3]));
        }
#pragma unroll
        for (int o = 1; o <= 2; o <<= 1) {
            mx0 = fmaxf(mx0, __shfl_xor_sync(0xffffffffu, mx0, o));
            mx1 = fmaxf(mx1, __shfl_xor_sync(0xffffffffu, mx1, o));
        }
        const float mn0 = fmaxf(mrow[0], mx0), mn1 = fmaxf(mrow[1], mx1);
        const float f0 = __expf(mrow[0] - mn0), f1 = __expf(mrow[1] - mn1);
        float ps0 = 0.f, ps1 = 0.f;
#pragma unroll
        for (int nt = 0; nt < 4; nt++) {
            s[nt][0] = __expf(sv[nt][0] - mn0);
            s[nt][1] = __expf(sv[nt][1] - mn0);
            s[nt][2] = __expf(sv[nt][2] - mn1);
            s[nt][3] = __expf(sv[nt][3] - mn1);
            ps0 += s[nt][0] + s[nt][1];
            ps1 += s[nt][2] + s[nt][3];
        }
#pragma unroll
        for (int o = 1; o <= 2; o <<= 1) {
            ps0 += __shfl_xor_sync(0xffffffffu, ps0, o);
            ps1 += __shfl_xor_sync(0xffffffffu, ps1, o);
        }
        lrow[0] = lrow[0] * f0 + ps0;
        lrow[1] = lrow[1] * f1 + ps1;
        mrow[0] = mn0;
        mrow[1] = mn1;
#pragma unroll
        for (int dt = 0; dt < 16; dt++) {
            acc[dt][0] *= f0; acc[dt][1] *= f0;
            acc[dt][2] *= f1; acc[dt][3] *= f1;
        }

        // PV with permuted V rows (no shuffles)
#pragma unroll
        for (int ks = 0; ks < 4; ks++) {
            uint32_t af[4];
            af[0] = tf32r(s[ks][0]);
            af[1] = tf32r(s[ks][2]);
            af[2] = tf32r(s[ks][1]);
            af[3] = tf32r(s[ks][3]);
            const uint32_t* vp0 = Vb + (kw * 32 + ks * 8 + 2 * t4) * VP + g;
            const uint32_t* vp1 = vp0 + VP;
#pragma unroll
            for (int dt = 0; dt < 16; dt++) {
                uint32_t bf[2] = { vp0[dt * 8], vp1[dt * 8] };
                mma_tf32(acc[dt], af, bf);
            }
        }
        // no trailing barrier: next iteration's barrier provides the ordering
    }

    // ---- 2-way merge across kv-strips (overlay smem in Qs region) ----
    __syncthreads();
    float* ab = (float*)sf;          // [64][130]
    float* ml = (float*)sf + 64 * 130;
    const int r0 = qw * 16 + g, r1 = r0 + 8;

    if (kw == 1) {
#pragma unroll
        for (int dt = 0; dt < 16; dt++) {
            const int cb = dt * 8 + 2 * t4;
            ab[r0 * 130 + cb]     = acc[dt][0];
            ab[r0 * 130 + cb + 1] = acc[dt][1];
            ab[r1 * 130 + cb]     = acc[dt][2];
            ab[r1 * 130 + cb + 1] = acc[dt][3];
        }
        if (t4 == 0) {
            ml[r0 * 2] = mrow[0]; ml[r0 * 2 + 1] = lrow[0];
            ml[r1 * 2] = mrow[1]; ml[r1 * 2 + 1] = lrow[1];
        }
    }
    __syncthreads();
    if (kw == 0) {
        const float m1a = ml[r0 * 2], l1a = ml[r0 * 2 + 1];
        const float m1b = ml[r1 * 2], l1b = ml[r1 * 2 + 1];
        const float mf0 = fmaxf(mrow[0], m1a), mf1 = fmaxf(mrow[1], m1b);
        const float e00 = __expf(mrow[0] - mf0), e01 = __expf(m1a - mf0);
        const float e10 = __expf(mrow[1] - mf1), e11 = __expf(m1b - mf1);
        const float lf0 = lrow[0] * e00 + l1a * e01;
        const float lf1 = lrow[1] * e10 + l1b * e11;
        const float i0 = (mf0 <= -1e29f) ? 0.f : 1.f / lf0;
        const float i1 = (mf1 <= -1e29f) ? 0.f : 1.f / lf1;
        float* o0p = O + (size_t)(b * QL_ + q0 + r0) * D_ + h * HD_;
        float* o1p = O + (size_t)(b * QL_ + q0 + r1) * D_ + h * HD_;
#pragma unroll
        for (int dt = 0; dt < 16; dt++) {
            const int cb = dt * 8 + 2 * t4;
            float x0 = (acc[dt][0] * e00 + ab[r0 * 130 + cb]     * e01) * i0;
            float x1 = (acc[dt][1] * e00 + ab[r0 * 130 + cb + 1] * e01) * i0;
            float x2 = (acc[dt][2] * e10 + ab[r1 * 130 + cb]     * e11) * i1;
            float x3 = (acc[dt][3] * e10 + ab[r1 * 130 + cb + 1] * e11) * i1;
            // tf32-round O so the final GEMM's rna at load is a no-op on it
            *(float2*)(o0p + cb) = make_float2(tf32rf(x0), tf32rf(x1));
            *(float2*)(o1p + cb) = make_float2(tf32rf(x2), tf32rf(x3));
        }
    }
}

// ===========================================================================
// Launch (prepass deleted — rounding folded into GEMM fragment loads)
// ===========================================================================
extern "C" void kernel_launch(void* const* d_in, const int* in_sizes, int n_in,
                              void* d_out, int out_size)
{
    const float* inq  = (const float*)d_in[0];
    const float* ink  = (const float*)d_in[1];
    const float* invv = (const float*)d_in[2];
    const int*   mask = (const int*)d_in[3];
    const float* Wq = (const float*)d_in[4];
    const float* bq = (const float*)d_in[5];
    const float* Wk = (const float*)d_in[6];
    const float* bk = (const float*)d_in[7];
    const float* Wv = (const float*)d_in[8];
    const float* bv = (const float*)d_in[9];
    const float* Wf = (const float*)d_in[10];
    const float* bf = (const float*)d_in[11];
    float* out = (float*)d_out;

    float *Qp, *Kp, *Vp, *Op;
    cudaGetSymbolAddress((void**)&Qp, g_Q);
    cudaGetSymbolAddress((void**)&Kp, g_K);
    cudaGetSymbolAddress((void**)&Vp, g_V);
    cudaGetSymbolAddress((void**)&Op, g_O);

    cudaFuncSetAttribute(gemm_tf32,
                         cudaFuncAttributeMaxDynamicSharedMemorySize, GEMM_SMEM);
    cudaFuncSetAttribute(flash_mma,
                         cudaFuncAttributeMaxDynamicSharedMemorySize, FL_SMEM);

    // Projections (raw inputs; rna at fragment load; tf32-rounded outputs)
    gemm_tf32<<<dim3(D_ / 128, (B_ * QL_) / 128), 256, GEMM_SMEM>>>(
        inq, Wq, bq, Qp, B_ * QL_, D_, D_, 1);
    gemm_tf32<<<dim3(D_ / 128, (B_ * KL_) / 128), 256, GEMM_SMEM>>>(
        ink, Wk, bk, Kp, B_ * KL_, D_, D_, 1);
    gemm_tf32<<<dim3(D_ / 128, (B_ * KL_) / 128), 256, GEMM_SMEM>>>(
        invv, Wv, bv, Vp, B_ * KL_, D_, D_, 1);

    // Attention (tensor-core flash, Q-in-registers, 1 barrier/tile)
    flash_mma<<<dim3(B_ * H_, QL_ / QT), 256, FL_SMEM>>>(mask, Op);

    // Output projection (fp32 store)
    gemm_tf32<<<dim3(D_ / 128, (B_ * QL_) / 128), 256, GEMM_SMEM>>>(
        Op, Wf, bf, out, B_ * QL_, D_, D_, 0);
}

// round 14
// speedup vs baseline: 1.0698x; 1.0698x over previous
#include <cuda_runtime.h>
#include <cstdint>

// Problem constants
#define B_   2
#define QL_  512
#define KL_  8192
#define D_   1024
#define H_   8
#define HD_  128

// Scratch (device globals — no allocations allowed)
__device__ float g_Q[B_ * QL_ * D_];
__device__ float g_K[B_ * KL_ * D_];
__device__ float g_V[B_ * KL_ * D_];
__device__ float g_O[B_ * QL_ * D_];
// tf32-pre-rounded copies of GEMM inputs
__device__ float g_rQin[B_ * QL_ * D_];
__device__ float g_rKin[B_ * KL_ * D_];
__device__ float g_rVin[B_ * KL_ * D_];
__device__ float g_rWq[D_ * D_];
__device__ float g_rWk[D_ * D_];
__device__ float g_rWv[D_ * D_];
__device__ float g_rWf[D_ * D_];

// fp32 -> tf32 round-to-nearest (unbiased)
__device__ __forceinline__ uint32_t tf32r(float x) {
    uint32_t u;
    asm("cvt.rna.tf32.f32 %0, %1;" : "=r"(u) : "f"(x));
    return u;
}
__device__ __forceinline__ float tf32rf(float x) {
    return __uint_as_float(tf32r(x));
}
__device__ __forceinline__ uint32_t smem_u32(const void* p) {
    uint32_t a;
    asm("{ .reg .u64 t; cvta.to.shared.u64 t, %1; cvt.u32.u64 %0, t; }"
        : "=r"(a) : "l"(p));
    return a;
}

// m16n8k8 tf32 MMA
__device__ __forceinline__ void mma_tf32(float* c, const uint32_t* a,
                                         const uint32_t* b) {
    asm volatile(
        "mma.sync.aligned.m16n8k8.row.col.f32.tf32.tf32.f32 "
        "{%0,%1,%2,%3}, {%4,%5,%6,%7}, {%8,%9}, {%0,%1,%2,%3};"
        : "+f"(c[0]), "+f"(c[1]), "+f"(c[2]), "+f"(c[3])
        : "r"(a[0]), "r"(a[1]), "r"(a[2]), "r"(a[3]), "r"(b[0]), "r"(b[1]));
}

// ldmatrix: tf32 fragment tiles are pairs of 8x8 b16 matrices
#define LDSM4(r, a) \
    asm volatile("ldmatrix.sync.aligned.m8n8.x4.shared.b16 {%0,%1,%2,%3}, [%4];" \
        : "=r"((r)[0]), "=r"((r)[1]), "=r"((r)[2]), "=r"((r)[3]) : "r"(a))
#define LDSM2(r, a) \
    asm volatile("ldmatrix.sync.aligned.m8n8.x2.shared.b16 {%0,%1}, [%2];" \
        : "=r"((r)[0]), "=r"((r)[1]) : "r"(a))

#define CPA16(dst, src) \
    asm volatile("cp.async.cg.shared.global [%0], [%1], 16;" \
                 :: "r"(dst), "l"(src) : "memory")
#define CPA_COMMIT() asm volatile("cp.async.commit_group;" ::: "memory")
#define CPA_WAIT(n)  asm volatile("cp.async.wait_group %0;" :: "n"(n) : "memory")

// ===========================================================================
// Prepass: elementwise tf32 rounding (float4 granularity)
// ===========================================================================
__global__ void round_pass(const float4* __restrict__ in,
                           float4* __restrict__ out, int n4)
{
    int i = blockIdx.x * blockDim.x + threadIdx.x;
    if (i < n4) {
        float4 v = in[i];
        out[i] = make_float4(tf32rf(v.x), tf32rf(v.y), tf32rf(v.z), tf32rf(v.w));
    }
}

// ===========================================================================
// tf32 mma.sync GEMM v4: 3-stage cp.async pipeline, PRE-ROUNDED inputs
// (raw fragment bits), ldmatrix fragment loads (96 -> 32 issue/thread/chunk).
// 2 CTAs/SM. C = A @ W^T + bias; round_store=1 -> tf32-rounded output.
// ===========================================================================
#define KC    32
#define APAD  36
#define STW   (128 * APAD)
#define GEMM_SMEM (6 * STW * 4)

__global__ __launch_bounds__(256, 2) void gemm_tf32(
    const float* __restrict__ A, const float* __restrict__ W,
    const float* __restrict__ bias, float* __restrict__ C,
    int M, int N, int K, int round_store)
{
    extern __shared__ __align__(16) uint32_t sg[];
    const uint32_t sb = smem_u32(sg);
    const uint32_t B_OFF = 3 * STW * 4;
    const uint32_t ST_B  = STW * 4;

    const int t = threadIdx.x, wid = t >> 5, lane = t & 31;
    const int g = lane >> 2, t4 = lane & 3;
    const int m0 = blockIdx.y * 128, n0 = blockIdx.x * 128;
    const int mw = (wid >> 2) * 64;
    const int nw = (wid & 3) * 32;

    // ldmatrix per-lane address offsets (bytes, within a stage)
    const int lm = lane & 15;
    const uint32_t afrag = (uint32_t)((mw + lm) * APAD + ((lane >> 4) << 2)) * 4;
    const uint32_t bfrag = (uint32_t)((nw + (lm & 7)) * APAD + ((lm >> 3) << 2)) * 4;

    float acc[4][4][4];
#pragma unroll
    for (int mt = 0; mt < 4; mt++)
#pragma unroll
        for (int nt = 0; nt < 4; nt++)
#pragma unroll
            for (int q = 0; q < 4; q++) acc[mt][nt][q] = 0.f;

    const int r  = t >> 3;
    const int c4 = (t & 7) * 4;
    size_t   gA[4], gB[4];
    uint32_t so4[4];
#pragma unroll
    for (int i = 0; i < 4; i++) {
        int ri = r + i * 32;
        gA[i]  = (size_t)(m0 + ri) * K + c4;
        gB[i]  = (size_t)(n0 + ri) * K + c4;
        so4[i] = (uint32_t)(ri * APAD + c4) * 4;
    }

    const int NC = K / KC;

#pragma unroll
    for (int s = 0; s < 2; s++) {
#pragma unroll
        for (int i = 0; i < 4; i++) {
            CPA16(sb + s * ST_B + so4[i],         A + gA[i] + s * KC);
            CPA16(sb + B_OFF + s * ST_B + so4[i], W + gB[i] + s * KC);
        }
        CPA_COMMIT();
    }

    for (int c = 0; c < NC; c++) {
        if (c + 1 < NC) { CPA_WAIT(1); } else { CPA_WAIT(0); }
        __syncthreads();

        if (c + 2 < NC) {
            const int st = (c + 2) % 3;
            const size_t k2 = (size_t)(c + 2) * KC;
#pragma unroll
            for (int i = 0; i < 4; i++) {
                CPA16(sb + st * ST_B + so4[i],         A + gA[i] + k2);
                CPA16(sb + B_OFF + st * ST_B + so4[i], W + gB[i] + k2);
            }
            CPA_COMMIT();
        }

        const uint32_t stA = sb + (c % 3) * ST_B;
        const uint32_t stB = sb + B_OFF + (c % 3) * ST_B;
#pragma unroll
        for (int ks = 0; ks < 4; ks++) {
            const uint32_t kb4 = (uint32_t)(ks * 8) * 4;
            uint32_t af[4][4], bf[4][2];
#pragma unroll
            for (int mt = 0; mt < 4; mt++)
                LDSM4(af[mt], stA + afrag + (uint32_t)(mt * 16 * APAD) * 4 + kb4);
#pragma unroll
            for (int nt = 0; nt < 4; nt++)
                LDSM2(bf[nt], stB + bfrag + (uint32_t)(nt * 8 * APAD) * 4 + kb4);
#pragma unroll
            for (int mt = 0; mt < 4; mt++)
#pragma unroll
                for (int nt = 0; nt < 4; nt++)
                    mma_tf32(acc[mt][nt], af[mt], bf[nt]);
        }
    }

#pragma unroll
    for (int mt = 0; mt < 4; mt++) {
#pragma unroll
        for (int nt = 0; nt < 4; nt++) {
            const int row = m0 + mw + mt * 16 + g;
            const int col = n0 + nw + nt * 8 + 2 * t4;
            float2 bb = *(const float2*)(bias + col);
            float o0 = acc[mt][nt][0] + bb.x, o1 = acc[mt][nt][1] + bb.y;
            float o2 = acc[mt][nt][2] + bb.x, o3 = acc[mt][nt][3] + bb.y;
            if (round_store) {
                o0 = tf32rf(o0); o1 = tf32rf(o1);
                o2 = tf32rf(o2); o3 = tf32rf(o3);
            }
            *(float2*)(C + (size_t)row * N + col) = make_float2(o0, o1);
            *(float2*)(C + (size_t)(row + 8) * N + col) = make_float2(o2, o3);
        }
    }
}

// ===========================================================================
// Flash attention v5: Q-in-registers + 1 barrier/tile + ldmatrix K loads.
// 256 threads, 8 warps = 4 q-groups x 2 kv-strips; KT=64 double-buffered.
// Q/K/V pre-rounded tf32 -> raw fragment bits. PV permuted-V (no shuffles).
// ===========================================================================
#define QT   64
#define KT   64
#define QP   132
#define KP   132
#define VP   132
#define KBUF (KT * KP)
#define VBUF (KT * VP)
#define FL_WORDS (QT * QP + 2 * KBUF + 2 * VBUF)  // 42240
#define FL_SMEM  (FL_WORDS * 4)                   // 168960

__global__ __launch_bounds__(256, 1) void flash_mma(
    const int* __restrict__ mask, float* __restrict__ O)
{
    extern __shared__ __align__(16) uint32_t sf[];
    uint32_t* Qs = sf;
    uint32_t* Vs = sf + QT * QP + 2 * KBUF;
    const uint32_t sb   = smem_u32(sf);
    const uint32_t ks_b = sb + QT * QP * 4;
    const uint32_t vs_b = sb + (QT * QP + 2 * KBUF) * 4;

    const int b  = blockIdx.x >> 3, h = blockIdx.x & 7;
    const int q0 = blockIdx.y * QT;
    const int t = threadIdx.x, wid = t >> 5, lane = t & 31;
    const int g = lane >> 2, t4 = lane & 3;
    const int qw = wid >> 1;
    const int kw = wid & 1;
    const int qrow = qw * 16 + g;
    const int lm = lane & 15;
    // ldmatrix offset for K fragments (bytes, within one K buffer)
    const uint32_t kfrag = (uint32_t)((kw * 32 + (lm & 7)) * KP
                                      + ((lm >> 3) << 2)) * 4;

    // Load Q tile to SMEM
    {
        const size_t qbase = (size_t)(b * QL_ + q0) * D_ + h * HD_;
#pragma unroll
        for (int i = 0; i < 8; i++) {
            int v = t + i * 256, r = v >> 5, d4 = (v & 31) << 2;
            *(uint4*)(Qs + r * QP + d4) =
                *(const uint4*)(g_Q + qbase + (size_t)r * D_ + d4);
        }
    }
    __syncthreads();

    // Q fragments -> registers, once (loop-invariant)
    uint32_t qf[16][4];
#pragma unroll
    for (int ks = 0; ks < 16; ks++) {
        const uint32_t* qp = Qs + qrow * QP + ks * 8 + t4;
        qf[ks][0] = qp[0];
        qf[ks][1] = qp[8 * QP];
        qf[ks][2] = qp[4];
        qf[ks][3] = qp[8 * QP + 4];
    }

    const int lr  = t >> 5;
    const int ld4 = (t & 31) << 2;
    const size_t kvbase = (size_t)(b * KL_) * D_ + h * HD_;

    float acc[16][4];
#pragma unroll
    for (int dt = 0; dt < 16; dt++)
#pragma unroll
        for (int q = 0; q < 4; q++) acc[dt][q] = 0.f;
    float mrow[2] = {-1e30f, -1e30f}, lrow[2] = {0.f, 0.f};

    const float scale = 0.08838834764831845f;
    const int* mp0 = mask + (size_t)(b * QL_ + q0 + qrow) * KL_;
    const int* mp1 = mp0 + 8 * KL_;

    // prologue: tile 0 -> buf 0
#pragma unroll
    for (int i = 0; i < 8; i++) {
        int r = lr + i * 8;
        CPA16(ks_b + (r * KP + ld4) * 4, g_K + kvbase + (size_t)r * D_ + ld4);
    }
#pragma unroll
    for (int i = 0; i < 8; i++) {
        int r = lr + i * 8;
        CPA16(vs_b + (r * VP + ld4) * 4, g_V + kvbase + (size_t)r * D_ + ld4);
    }
    CPA_COMMIT();

    const int NT = KL_ / KT;   // 128
    for (int c = 0; c < NT; c++) {
        CPA_WAIT(0);
        __syncthreads();   // tile c visible; all warps done reading buf (c+1)&1

        if (c + 1 < NT) {
            const int buf = (c + 1) & 1;
            const size_t rb = kvbase + (size_t)(c + 1) * KT * D_;
#pragma unroll
            for (int i = 0; i < 8; i++) {
                int r = lr + i * 8;
                CPA16(ks_b + (buf * KBUF + r * KP + ld4) * 4,
                      g_K + rb + (size_t)r * D_ + ld4);
            }
#pragma unroll
            for (int i = 0; i < 8; i++) {
                int r = lr + i * 8;
                CPA16(vs_b + (buf * VBUF + r * VP + ld4) * 4,
                      g_V + rb + (size_t)r * D_ + ld4);
            }
            CPA_COMMIT();
        }

        const uint32_t kstage = ks_b + (uint32_t)(c & 1) * (KBUF * 4);
        const uint32_t* Vb = Vs + (c & 1) * VBUF;
        const int kvt = c * KT + kw * 32;

        int2 mk0[4], mk1[4];
#pragma unroll
        for (int nt = 0; nt < 4; nt++) {
            const int col = kvt + nt * 8 + 2 * t4;
            mk0[nt] = *(const int2*)(mp0 + col);
            mk1[nt] = *(const int2*)(mp1 + col);
        }

        // S = Q . K^T (Q from registers; K via ldmatrix.x2)
        float s[4][4];
#pragma unroll
        for (int nt = 0; nt < 4; nt++)
#pragma unroll
            for (int q = 0; q < 4; q++) s[nt][q] = 0.f;
#pragma unroll
        for (int ks = 0; ks < 16; ks++) {
            const uint32_t kb4 = (uint32_t)(ks * 8) * 4;
#pragma unroll
            for (int nt = 0; nt < 4; nt++) {
                uint32_t bf[2];
                LDSM2(bf, kstage + kfrag + (uint32_t)(nt * 8 * KP) * 4 + kb4);
                mma_tf32(s[nt], qf[ks], bf);
            }
        }

        // mask + online softmax
        float mx0 = -1e30f, mx1 = -1e30f;
        float sv[4][4];
#pragma unroll
        for (int nt = 0; nt < 4; nt++) {
            sv[nt][0] = mk0[nt].x ? s[nt][0] * scale : -1e30f;
            sv[nt][1] = mk0[nt].y ? s[nt][1] * scale : -1e30f;
            sv[nt][2] = mk1[nt].x ? s[nt][2] * scale : -1e30f;
            sv[nt][3] = mk1[nt].y ? s[nt][3] * scale : -1e30f;
            mx0 = fmaxf(mx0, fmaxf(sv[nt][0], sv[nt][1]));
            mx1 = fmaxf(mx1, fmaxf(sv[nt][2], sv[nt][3]));
        }
#pragma unroll
        for (int o = 1; o <= 2; o <<= 1) {
            mx0 = fmaxf(mx0, __shfl_xor_sync(0xffffffffu, mx0, o));
            mx1 = fmaxf(mx1, __shfl_xor_sync(0xffffffffu, mx1, o));
        }
        const float mn0 = fmaxf(mrow[0], mx0), mn1 = fmaxf(mrow[1], mx1);
        const float f0 = __expf(mrow[0] - mn0), f1 = __expf(mrow[1] - mn1);
        float ps0 = 0.f, ps1 = 0.f;
#pragma unroll
        for (int nt = 0; nt < 4; nt++) {
            s[nt][0] = __expf(sv[nt][0] - mn0);
            s[nt][1] = __expf(sv[nt][1] - mn0);
            s[nt][2] = __expf(sv[nt][2] - mn1);
            s[nt][3] = __expf(sv[nt][3] - mn1);
            ps0 += s[nt][0] + s[nt][1];
            ps1 += s[nt][2] + s[nt][3];
        }
#pragma unroll
        for (int o = 1; o <= 2; o <<= 1) {
            ps0 += __shfl_xor_sync(0xffffffffu, ps0, o);
            ps1 += __shfl_xor_sync(0xffffffffu, ps1, o);
        }
        lrow[0] = lrow[0] * f0 + ps0;
        lrow[1] = lrow[1] * f1 + ps1;
        mrow[0] = mn0;
        mrow[1] = mn1;
#pragma unroll
        for (int dt = 0; dt < 16; dt++) {
            acc[dt][0] *= f0; acc[dt][1] *= f0;
            acc[dt][2] *= f1; acc[dt][3] *= f1;
        }

        // PV with permuted V rows (no shuffles)
#pragma unroll
        for (int ks = 0; ks < 4; ks++) {
            uint32_t af[4];
            af[0] = tf32r(s[ks][0]);
            af[1] = tf32r(s[ks][2]);
            af[2] = tf32r(s[ks][1]);
            af[3] = tf32r(s[ks][3]);
            const uint32_t* vp0 = Vb + (kw * 32 + ks * 8 + 2 * t4) * VP + g;
            const uint32_t* vp1 = vp0 + VP;
#pragma unroll
            for (int dt = 0; dt < 16; dt++) {
                uint32_t bf[2] = { vp0[dt * 8], vp1[dt * 8] };
                mma_tf32(acc[dt], af, bf);
            }
        }
        // no trailing barrier: next iteration's barrier provides ordering
    }

    // ---- 2-way merge across kv-strips (overlay smem) ----
    __syncthreads();
    float* ab = (float*)sf;          // [64][130]
    float* ml = (float*)sf + 64 * 130;
    const int r0 = qw * 16 + g, r1 = r0 + 8;

    if (kw == 1) {
#pragma unroll
        for (int dt = 0; dt < 16; dt++) {
            const int cb = dt * 8 + 2 * t4;
            ab[r0 * 130 + cb]     = acc[dt][0];
            ab[r0 * 130 + cb + 1] = acc[dt][1];
            ab[r1 * 130 + cb]     = acc[dt][2];
            ab[r1 * 130 + cb + 1] = acc[dt][3];
        }
        if (t4 == 0) {
            ml[r0 * 2] = mrow[0]; ml[r0 * 2 + 1] = lrow[0];
            ml[r1 * 2] = mrow[1]; ml[r1 * 2 + 1] = lrow[1];
        }
    }
    __syncthreads();
    if (kw == 0) {
        const float m1a = ml[r0 * 2], l1a = ml[r0 * 2 + 1];
        const float m1b = ml[r1 * 2], l1b = ml[r1 * 2 + 1];
        const float mf0 = fmaxf(mrow[0], m1a), mf1 = fmaxf(mrow[1], m1b);
        const float e00 = __expf(mrow[0] - mf0), e01 = __expf(m1a - mf0);
        const float e10 = __expf(mrow[1] - mf1), e11 = __expf(m1b - mf1);
        const float lf0 = lrow[0] * e00 + l1a * e01;
        const float lf1 = lrow[1] * e10 + l1b * e11;
        const float i0 = (mf0 <= -1e29f) ? 0.f : 1.f / lf0;
        const float i1 = (mf1 <= -1e29f) ? 0.f : 1.f / lf1;
        float* o0p = O + (size_t)(b * QL_ + q0 + r0) * D_ + h * HD_;
        float* o1p = O + (size_t)(b * QL_ + q0 + r1) * D_ + h * HD_;
#pragma unroll
        for (int dt = 0; dt < 16; dt++) {
            const int cb = dt * 8 + 2 * t4;
            float x0 = (acc[dt][0] * e00 + ab[r0 * 130 + cb]     * e01) * i0;
            float x1 = (acc[dt][1] * e00 + ab[r0 * 130 + cb + 1] * e01) * i0;
            float x2 = (acc[dt][2] * e10 + ab[r1 * 130 + cb]     * e11) * i1;
            float x3 = (acc[dt][3] * e10 + ab[r1 * 130 + cb + 1] * e11) * i1;
            // tf32-round O so the final GEMM consumes it raw
            *(float2*)(o0p + cb) = make_float2(tf32rf(x0), tf32rf(x1));
            *(float2*)(o1p + cb) = make_float2(tf32rf(x2), tf32rf(x3));
        }
    }
}

// ===========================================================================
// Launch
// ===========================================================================
extern "C" void kernel_launch(void* const* d_in, const int* in_sizes, int n_in,
                              void* d_out, int out_size)
{
    const float* inq  = (const float*)d_in[0];
    const float* ink  = (const float*)d_in[1];
    const float* invv = (const float*)d_in[2];
    const int*   mask = (const int*)d_in[3];
    const float* Wq = (const float*)d_in[4];
    const float* bq = (const float*)d_in[5];
    const float* Wk = (const float*)d_in[6];
    const float* bk = (const float*)d_in[7];
    const float* Wv = (const float*)d_in[8];
    const float* bv = (const float*)d_in[9];
    const float* Wf = (const float*)d_in[10];
    const float* bf = (const float*)d_in[11];
    float* out = (float*)d_out;

    float *Qp, *Kp, *Vp, *Op;
    float *rQin, *rKin, *rVin, *rWq, *rWk, *rWv, *rWf;
    cudaGetSymbolAddress((void**)&Qp, g_Q);
    cudaGetSymbolAddress((void**)&Kp, g_K);
    cudaGetSymbolAddress((void**)&Vp, g_V);
    cudaGetSymbolAddress((void**)&Op, g_O);
    cudaGetSymbolAddress((void**)&rQin, g_rQin);
    cudaGetSymbolAddress((void**)&rKin, g_rKin);
    cudaGetSymbolAddress((void**)&rVin, g_rVin);
    cudaGetSymbolAddress((void**)&rWq, g_rWq);
    cudaGetSymbolAddress((void**)&rWk, g_rWk);
    cudaGetSymbolAddress((void**)&rWv, g_rWv);
    cudaGetSymbolAddress((void**)&rWf, g_rWf);

    cudaFuncSetAttribute(gemm_tf32,
                         cudaFuncAttributeMaxDynamicSharedMemorySize, GEMM_SMEM);
    cudaFuncSetAttribute(flash_mma,
                         cudaFuncAttributeMaxDynamicSharedMemorySize, FL_SMEM);

    // Prepass: round all GEMM inputs to tf32 once
    const int NQ4 = (B_ * QL_ * D_) / 4;
    const int NK4 = (B_ * KL_ * D_) / 4;
    const int NW4 = (D_ * D_) / 4;
    round_pass<<<NQ4 / 256, 256>>>((const float4*)inq,  (float4*)rQin, NQ4);
    round_pass<<<NK4 / 256, 256>>>((const float4*)ink,  (float4*)rKin, NK4);
    round_pass<<<NK4 / 256, 256>>>((const float4*)invv, (float4*)rVin, NK4);
    round_pass<<<NW4 / 256, 256>>>((const float4*)Wq,   (float4*)rWq,  NW4);
    round_pass<<<NW4 / 256, 256>>>((const float4*)Wk,   (float4*)rWk,  NW4);
    round_pass<<<NW4 / 256, 256>>>((const float4*)Wv,   (float4*)rWv,  NW4);
    round_pass<<<NW4 / 256, 256>>>((const float4*)Wf,   (float4*)rWf,  NW4);

    // Projections (pre-rounded inputs; ldmatrix GEMM; tf32-rounded outputs)
    gemm_tf32<<<dim3(D_ / 128, (B_ * QL_) / 128), 256, GEMM_SMEM>>>(
        rQin, rWq, bq, Qp, B_ * QL_, D_, D_, 1);
    gemm_tf32<<<dim3(D_ / 128, (B_ * KL_) / 128), 256, GEMM_SMEM>>>(
        rKin, rWk, bk, Kp, B_ * KL_, D_, D_, 1);
    gemm_tf32<<<dim3(D_ / 128, (B_ * KL_) / 128), 256, GEMM_SMEM>>>(
        rVin, rWv, bv, Vp, B_ * KL_, D_, D_, 1);

    // Attention (tensor-core flash, Q-in-regs, ldmatrix K, 1 barrier/tile)
    flash_mma<<<dim3(B_ * H_, QL_ / QT), 256, FL_SMEM>>>(mask, Op);

    // Output projection (Op already tf32-rounded; fp32 store)
    gemm_tf32<<<dim3(D_ / 128, (B_ * QL_) / 128), 256, GEMM_SMEM>>>(
        Op, rWf, bf, out, B_ * QL_, D_, D_, 0);
}